// round 2
// baseline (speedup 1.0000x reference)
#include <cuda_runtime.h>
#include <cstdint>

#define BATCH 4
#define NPTS  4096
#define DIM   512
#define K_NB  10

#define BM 128
#define BN 128
#define BK 32
#define SPAD 132   // padded row stride (floats) for smem tiles

// Scratch (no device allocation allowed):
__device__ __align__(16) float g_Hh[BATCH * NPTS * DIM];   // tf32 hi part (32 MB)
__device__ __align__(16) float g_Hl[BATCH * NPTS * DIM];   // tf32 lo part (32 MB)
__device__ int g_topk[BATCH * NPTS * K_NB];

__device__ __forceinline__ float tf32_rna(float x) {
    uint32_t y;
    asm("cvt.rna.tf32.f32 %0, %1;" : "=r"(y) : "f"(x));
    return __uint_as_float(y);
}

// ---------------------------------------------------------------------------
// K1: row-normalize H and split into tf32 hi/lo parts (one warp per row)
// ---------------------------------------------------------------------------
__global__ void normsplit_kernel(const float* __restrict__ H) {
    int row = (blockIdx.x * blockDim.x + threadIdx.x) >> 5;
    int lane = threadIdx.x & 31;
    if (row >= BATCH * NPTS) return;
    const float4* src = (const float4*)(H + (size_t)row * DIM);
    float4* dh = (float4*)(g_Hh + (size_t)row * DIM);
    float4* dl = (float4*)(g_Hl + (size_t)row * DIM);
    float ss = 0.f;
    float4 v[4];
#pragma unroll
    for (int j = 0; j < 4; j++) {
        v[j] = src[lane + 32 * j];
        ss += v[j].x * v[j].x + v[j].y * v[j].y + v[j].z * v[j].z + v[j].w * v[j].w;
    }
#pragma unroll
    for (int o = 16; o; o >>= 1) ss += __shfl_xor_sync(0xffffffffu, ss, o);
    float inv = 1.0f / fmaxf(sqrtf(ss), 1e-12f);
#pragma unroll
    for (int j = 0; j < 4; j++) {
        float w[4] = {v[j].x * inv, v[j].y * inv, v[j].z * inv, v[j].w * inv};
        float4 hi, lo;
        hi.x = tf32_rna(w[0]); lo.x = tf32_rna(w[0] - hi.x);
        hi.y = tf32_rna(w[1]); lo.y = tf32_rna(w[1] - hi.y);
        hi.z = tf32_rna(w[2]); lo.z = tf32_rna(w[2] - hi.z);
        hi.w = tf32_rna(w[3]); lo.w = tf32_rna(w[3] - hi.w);
        dh[lane + 32 * j] = hi;
        dl[lane + 32 * j] = lo;
    }
}

// ---------------------------------------------------------------------------
// K2: TF32 tensor-core Gram tile (3-term split, K=1536) + streaming top-10
//   grid = (NPTS/BM, BATCH), 256 threads (8 warps, 4x2 warp grid, 32x64 tiles)
// ---------------------------------------------------------------------------
__device__ __forceinline__ bool beats(float v, int vi, float w, int wi) {
    return (v > w) || (v == w && vi < wi);
}

__global__ void __launch_bounds__(256) simtopk_tc_kernel() {
    extern __shared__ __align__(16) float sm[];
    float* As   = sm;                        // [BK][SPAD]
    float* Bs   = As + BK * SPAD;            // [BK][SPAD]
    float* Ssim = Bs + BK * SPAD;            // [BM][SPAD]
    float* s_val = Ssim + BM * SPAD;         // [BM][K_NB] sorted asc (min at [0])
    int*   s_idx = (int*)(s_val + BM * K_NB);

    const int b = blockIdx.y;
    const int rowBase = blockIdx.x * BM;
    const int tid = threadIdx.x;
    const int warp = tid >> 5, lane = tid & 31;
    const int gid = lane >> 2, tig = lane & 3;
    const int warpM = warp >> 1, warpN = warp & 1;

    for (int i = tid; i < BM * K_NB; i += 256) {
        s_val[i] = -3.0e38f;
        s_idx[i] = 0x7fffffff;
    }
    __syncthreads();

    const size_t base = (size_t)b * NPTS * DIM;
    const int ldRow = tid & 127;       // row within tile this thread loads
    const int ldHalf = tid >> 7;       // which 16-float k-half

    for (int ct = 0; ct < NPTS; ct += BN) {
        float acc[2][8][4];
#pragma unroll
        for (int mt = 0; mt < 2; mt++)
#pragma unroll
            for (int nt = 0; nt < 8; nt++)
#pragma unroll
                for (int q = 0; q < 4; q++) acc[mt][nt][q] = 0.f;

        for (int kc = 0; kc < 3 * DIM; kc += BK) {
            const int seg = kc / DIM, kin = kc % DIM;
            const float* Asrc = (seg < 2 ? g_Hh : g_Hl) + base;
            const float* Bsrc = (seg == 1 ? g_Hl : g_Hh) + base;
            // stage A chunk transposed [k][m]
            {
                const float* src = Asrc + (size_t)(rowBase + ldRow) * DIM + kin + ldHalf * 16;
#pragma unroll
                for (int j = 0; j < 4; j++) {
                    float4 v = *(const float4*)(src + 4 * j);
                    int kk = ldHalf * 16 + 4 * j;
                    As[(kk + 0) * SPAD + ldRow] = v.x;
                    As[(kk + 1) * SPAD + ldRow] = v.y;
                    As[(kk + 2) * SPAD + ldRow] = v.z;
                    As[(kk + 3) * SPAD + ldRow] = v.w;
                }
                const float* srcB = Bsrc + (size_t)(ct + ldRow) * DIM + kin + ldHalf * 16;
#pragma unroll
                for (int j = 0; j < 4; j++) {
                    float4 v = *(const float4*)(srcB + 4 * j);
                    int kk = ldHalf * 16 + 4 * j;
                    Bs[(kk + 0) * SPAD + ldRow] = v.x;
                    Bs[(kk + 1) * SPAD + ldRow] = v.y;
                    Bs[(kk + 2) * SPAD + ldRow] = v.z;
                    Bs[(kk + 3) * SPAD + ldRow] = v.w;
                }
            }
            __syncthreads();
#pragma unroll
            for (int ks = 0; ks < BK / 8; ks++) {
                const int k0 = ks * 8;
                uint32_t a[2][4], bb[8][2];
#pragma unroll
                for (int mt = 0; mt < 2; mt++) {
                    const float* Ak0 = As + (k0 + tig) * SPAD + warpM * 32 + mt * 16 + gid;
                    const float* Ak4 = As + (k0 + tig + 4) * SPAD + warpM * 32 + mt * 16 + gid;
                    a[mt][0] = __float_as_uint(Ak0[0]);
                    a[mt][1] = __float_as_uint(Ak0[8]);
                    a[mt][2] = __float_as_uint(Ak4[0]);
                    a[mt][3] = __float_as_uint(Ak4[8]);
                }
#pragma unroll
                for (int nt = 0; nt < 8; nt++) {
                    const int n = warpN * 64 + nt * 8 + gid;
                    bb[nt][0] = __float_as_uint(Bs[(k0 + tig) * SPAD + n]);
                    bb[nt][1] = __float_as_uint(Bs[(k0 + tig + 4) * SPAD + n]);
                }
#pragma unroll
                for (int mt = 0; mt < 2; mt++)
#pragma unroll
                    for (int nt = 0; nt < 8; nt++) {
                        asm volatile(
                            "mma.sync.aligned.m16n8k8.row.col.f32.tf32.tf32.f32 "
                            "{%0,%1,%2,%3},{%4,%5,%6,%7},{%8,%9},{%0,%1,%2,%3};"
                            : "+f"(acc[mt][nt][0]), "+f"(acc[mt][nt][1]),
                              "+f"(acc[mt][nt][2]), "+f"(acc[mt][nt][3])
                            : "r"(a[mt][0]), "r"(a[mt][1]), "r"(a[mt][2]), "r"(a[mt][3]),
                              "r"(bb[nt][0]), "r"(bb[nt][1]));
                    }
            }
            __syncthreads();
        }

        // epilogue: dump sim tile to smem
#pragma unroll
        for (int mt = 0; mt < 2; mt++) {
            const int r0 = warpM * 32 + mt * 16 + gid;
#pragma unroll
            for (int nt = 0; nt < 8; nt++) {
                const int c = warpN * 64 + nt * 8 + 2 * tig;
                *(float2*)&Ssim[r0 * SPAD + c] = make_float2(acc[mt][nt][0], acc[mt][nt][1]);
                *(float2*)&Ssim[(r0 + 8) * SPAD + c] = make_float2(acc[mt][nt][2], acc[mt][nt][3]);
            }
        }
        __syncthreads();

        // top-10 fold: warp owns rows warp*16 .. +15
        for (int r = 0; r < 16; r++) {
            const int rowL = warp * 16 + r;
            float4 v4 = *(const float4*)&Ssim[rowL * SPAD + lane * 4];
            float vv[4] = {v4.x, v4.y, v4.z, v4.w};
#pragma unroll
            for (int c = 0; c < 4; c++) {
                float v = vv[c];
                int col = ct + lane * 4 + c;
                float tv = s_val[rowL * K_NB];
                int ti = s_idx[rowL * K_NB];
                unsigned m = __ballot_sync(0xffffffffu, beats(v, col, tv, ti));
                while (m) {
                    int src = __ffs(m) - 1;
                    m &= m - 1;
                    float cv = __shfl_sync(0xffffffffu, v, src);
                    int ci = __shfl_sync(0xffffffffu, col, src);
                    if (lane == 0) {
                        float* lv = s_val + rowL * K_NB;
                        int* li = s_idx + rowL * K_NB;
                        if (beats(cv, ci, lv[0], li[0])) {
                            int j = 0;
                            while (j < K_NB - 1 && beats(cv, ci, lv[j + 1], li[j + 1])) {
                                lv[j] = lv[j + 1]; li[j] = li[j + 1]; j++;
                            }
                            lv[j] = cv; li[j] = ci;
                        }
                    }
                    __syncwarp();
                }
            }
        }
        __syncthreads();
    }

    for (int i = tid; i < BM * K_NB; i += 256)
        g_topk[((size_t)b * NPTS + rowBase) * K_NB + i] = s_idx[i];
}

// ---------------------------------------------------------------------------
// K3: zero output; K4: scatter s = 1/11 (+s at diagonal)
// ---------------------------------------------------------------------------
__global__ void zero_kernel(float4* __restrict__ out, size_t n4) {
    size_t i = (size_t)blockIdx.x * blockDim.x + threadIdx.x;
    size_t stride = (size_t)gridDim.x * blockDim.x;
    float4 z = make_float4(0.f, 0.f, 0.f, 0.f);
    for (; i < n4; i += stride) out[i] = z;
}

__global__ void scatter_kernel(float* __restrict__ out) {
    int row = blockIdx.x * blockDim.x + threadIdx.x;
    if (row >= BATCH * NPTS) return;
    int i = row & (NPTS - 1);
    float* dst = out + (size_t)row * NPTS;
    const int* idx = g_topk + (size_t)row * K_NB;
    const float s = 1.0f / 11.0f;
#pragma unroll
    for (int k = 0; k < K_NB; k++) dst[idx[k]] = s;
    dst[i] += s;
}

// ---------------------------------------------------------------------------
extern "C" void kernel_launch(void* const* d_in, const int* in_sizes, int n_in,
                              void* d_out, int out_size) {
    const float* H = (const float*)d_in[0];
    float* out = (float*)d_out;

    normsplit_kernel<<<(BATCH * NPTS * 32 + 255) / 256, 256>>>(H);

    const size_t smem_bytes =
        (size_t)(BK * SPAD * 2 + BM * SPAD + BM * K_NB) * sizeof(float) +
        (size_t)(BM * K_NB) * sizeof(int);
    cudaFuncSetAttribute(simtopk_tc_kernel,
                         cudaFuncAttributeMaxDynamicSharedMemorySize,
                         (int)smem_bytes);
    dim3 g2(NPTS / BM, BATCH);
    simtopk_tc_kernel<<<g2, 256, smem_bytes>>>();

    size_t n4 = (size_t)BATCH * NPTS * NPTS / 4;
    zero_kernel<<<16384, 256>>>((float4*)out, n4);

    scatter_kernel<<<(BATCH * NPTS + 255) / 256, 256>>>(out);
}

// round 5
// speedup vs baseline: 3.4455x; 3.4455x over previous
#include <cuda_runtime.h>
#include <cuda_bf16.h>
#include <cstdint>

#define BATCH 4
#define NPTS  4096
#define DIM   512
#define KSPLIT 1024          // hi(512) || lo(512) bf16 per row
#define K_NB  10

#define BM 128
#define BN 128
#define KC 64                // bf16 per K-chunk = 128 B per row
#define NSTAGE 4
#define A_BYTES (BM * 128)                  // 16 KB
#define STAGE_BYTES (2 * A_BYTES)           // A + B = 32 KB
#define N_COLTILES (NPTS / BN)              // 32
#define N_KCHUNKS  24                       // 3 segments x 8 chunks (K=1536)
#define SPAD 132

__device__ __align__(16) __nv_bfloat16 g_Hsplit[(size_t)BATCH * NPTS * KSPLIT]; // 32 MB
__device__ int g_topk[BATCH * NPTS * K_NB];

__device__ __forceinline__ uint32_t smem_u32(const void* p) {
    uint32_t a;
    asm("{ .reg .u64 t; cvta.to.shared.u64 t, %1; cvt.u32.u64 %0, t; }" : "=r"(a) : "l"(p));
    return a;
}
__device__ __forceinline__ void cp16(uint32_t dst, const void* src) {
    asm volatile("cp.async.cg.shared.global [%0], [%1], 16;" :: "r"(dst), "l"(src));
}
__device__ __forceinline__ void cp_commit() {
    asm volatile("cp.async.commit_group;" ::: "memory");
}
template <int N>
__device__ __forceinline__ void cp_wait() {
    asm volatile("cp.async.wait_group %0;" :: "n"(N) : "memory");
}
__device__ __forceinline__ void ldsm4(uint32_t* r, uint32_t addr) {
    asm volatile("ldmatrix.sync.aligned.m8n8.x4.shared.b16 {%0,%1,%2,%3}, [%4];"
                 : "=r"(r[0]), "=r"(r[1]), "=r"(r[2]), "=r"(r[3]) : "r"(addr));
}
__device__ __forceinline__ void mma16816(float* c, const uint32_t* a, uint32_t b0, uint32_t b1) {
    asm volatile(
        "mma.sync.aligned.m16n8k16.row.col.f32.bf16.bf16.f32 "
        "{%0,%1,%2,%3},{%4,%5,%6,%7},{%8,%9},{%0,%1,%2,%3};"
        : "+f"(c[0]), "+f"(c[1]), "+f"(c[2]), "+f"(c[3])
        : "r"(a[0]), "r"(a[1]), "r"(a[2]), "r"(a[3]), "r"(b0), "r"(b1));
}

// ---------------------------------------------------------------------------
// K1: row-normalize + bf16 hi/lo split  (one warp per row)
// ---------------------------------------------------------------------------
__global__ void normsplit_kernel(const float* __restrict__ H) {
    int row = (blockIdx.x * blockDim.x + threadIdx.x) >> 5;
    int lane = threadIdx.x & 31;
    if (row >= BATCH * NPTS) return;
    const float4* src = (const float4*)(H + (size_t)row * DIM);
    float ss = 0.f;
    float4 v[4];
#pragma unroll
    for (int j = 0; j < 4; j++) {
        v[j] = src[lane + 32 * j];
        ss += v[j].x * v[j].x + v[j].y * v[j].y + v[j].z * v[j].z + v[j].w * v[j].w;
    }
#pragma unroll
    for (int o = 16; o; o >>= 1) ss += __shfl_xor_sync(0xffffffffu, ss, o);
    float inv = 1.0f / fmaxf(sqrtf(ss), 1e-12f);
    __nv_bfloat16* dst = g_Hsplit + (size_t)row * KSPLIT;
#pragma unroll
    for (int j = 0; j < 4; j++) {
        float w[4] = {v[j].x * inv, v[j].y * inv, v[j].z * inv, v[j].w * inv};
        __nv_bfloat16 hi[4], lo[4];
#pragma unroll
        for (int q = 0; q < 4; q++) {
            hi[q] = __float2bfloat16_rn(w[q]);
            lo[q] = __float2bfloat16_rn(w[q] - __bfloat162float(hi[q]));
        }
        int off = 4 * lane + 128 * j;
        __nv_bfloat162 h0; h0.x = hi[0]; h0.y = hi[1];
        __nv_bfloat162 h1; h1.x = hi[2]; h1.y = hi[3];
        __nv_bfloat162 l0; l0.x = lo[0]; l0.y = lo[1];
        __nv_bfloat162 l1; l1.x = lo[2]; l1.y = lo[3];
        *(__nv_bfloat162*)(dst + off) = h0;
        *(__nv_bfloat162*)(dst + off + 2) = h1;
        *(__nv_bfloat162*)(dst + off + DIM) = l0;
        *(__nv_bfloat162*)(dst + off + DIM + 2) = l1;
    }
}

// ---------------------------------------------------------------------------
// K2: bf16 mma.sync Gram, 3-segment K=1536:
//     A segs [hi, hi, lo]  x  B segs [hi, lo, hi]
//     = hi.hi' + hi.lo' + lo.hi'   (lo.lo' ~ 7e-8 dropped)
//   grid (32, 4), 256 threads; warp grid 2(M) x 4(N); warp tile 64x32
// ---------------------------------------------------------------------------
__device__ __forceinline__ bool beats(float v, int vi, float w, int wi) {
    return (v > w) || (v == w && vi < wi);
}

__global__ void __launch_bounds__(256, 1) gram_topk_kernel() {
    extern __shared__ __align__(16) unsigned char rawsm[];
    unsigned char* dynp = (unsigned char*)(((uintptr_t)rawsm + 1023) & ~(uintptr_t)1023);
    const uint32_t smA = smem_u32(dynp);
    float* Ssim  = (float*)(dynp + NSTAGE * STAGE_BYTES);
    float* s_val = Ssim + BM * SPAD;
    int*   s_idx = (int*)(s_val + BM * K_NB);

    const int b = blockIdx.y;
    const int rowBase = blockIdx.x * BM;
    const int tid = threadIdx.x;
    const int warp = tid >> 5, lane = tid & 31;
    const int wM = warp >> 2, wN = warp & 3;

    // ldmatrix per-lane address components (SW128: xor pattern = (row&7)<<4)
    const uint32_t aRowByte = (uint32_t)(wM * 64 + (lane & 15)) * 128;
    const uint32_t aK = (lane >> 4) * 16;
    const uint32_t bRowByte = (uint32_t)(wN * 32 + ((lane >> 4) << 3) + (lane & 7)) * 128;
    const uint32_t bK = ((lane >> 3) & 1) * 16;
    const uint32_t xr = (lane & 7) << 4;

    for (int i = tid; i < BM * K_NB; i += 256) {
        s_val[i] = -3.0e38f;
        s_idx[i] = 0x7fffffff;
    }
    __syncthreads();

    const __nv_bfloat16* __restrict__ gsrc = g_Hsplit + (size_t)b * NPTS * KSPLIT;

    const int ldRow0 = tid >> 3;       // +32*i
    const int ldSeg = tid & 7;
    const uint32_t ldDstOff = (uint32_t)(ldSeg * 16);

    // 3-segment source offsets: seg = kc>>3, kin = (kc&7)*KC
    //   A: seg 0,1 -> hi (offset 0), seg 2 -> lo (offset DIM)
    //   B: seg 0,2 -> hi,            seg 1 -> lo
    auto issue_chunk = [&](int ct, int kc) {
        const uint32_t st = smA + (kc & (NSTAGE - 1)) * STAGE_BYTES;
        const int colBase = ct * BN;
        const int seg = kc >> 3;
        const int kin = (kc & 7) * KC + ldSeg * 8;
        const int aOf = (seg == 2) ? DIM : 0;
        const int bOf = (seg == 1) ? DIM : 0;
#pragma unroll
        for (int i = 0; i < 4; i++) {
            int row = ldRow0 + 32 * i;
            uint32_t d = (uint32_t)row * 128 + (ldDstOff ^ ((row & 7) << 4));
            cp16(st + d, gsrc + (size_t)(rowBase + row) * KSPLIT + aOf + kin);
            cp16(st + A_BYTES + d, gsrc + (size_t)(colBase + row) * KSPLIT + bOf + kin);
        }
        cp_commit();
    };

    float acc[4][4][4];

    issue_chunk(0, 0); issue_chunk(0, 1); issue_chunk(0, 2);

    for (int ct = 0; ct < N_COLTILES; ct++) {
#pragma unroll
        for (int mt = 0; mt < 4; mt++)
#pragma unroll
            for (int nt = 0; nt < 4; nt++)
#pragma unroll
                for (int q = 0; q < 4; q++) acc[mt][nt][q] = 0.f;

        for (int kc = 0; kc < N_KCHUNKS; kc++) {
            const int rem = N_KCHUNKS - 1 - kc;
            if (rem >= 2) cp_wait<2>();
            else if (rem == 1) cp_wait<1>();
            else cp_wait<0>();
            __syncthreads();
            if (kc + 3 < N_KCHUNKS) issue_chunk(ct, kc + 3);

            const uint32_t Ast = smA + (kc & (NSTAGE - 1)) * STAGE_BYTES;
            const uint32_t Bst = Ast + A_BYTES;
#pragma unroll
            for (int ks = 0; ks < KC / 16; ks++) {
                uint32_t a[4][4], bf[2][4];
#pragma unroll
                for (int mt = 0; mt < 4; mt++)
                    ldsm4(a[mt], Ast + aRowByte + mt * 2048 + ((ks * 32 + aK) ^ xr));
#pragma unroll
                for (int np = 0; np < 2; np++)
                    ldsm4(bf[np], Bst + bRowByte + np * 2048 + ((ks * 32 + bK) ^ xr));
#pragma unroll
                for (int mt = 0; mt < 4; mt++)
#pragma unroll
                    for (int np = 0; np < 2; np++) {
                        mma16816(acc[mt][np * 2 + 0], a[mt], bf[np][0], bf[np][1]);
                        mma16816(acc[mt][np * 2 + 1], a[mt], bf[np][2], bf[np][3]);
                    }
            }
        }

        // prefetch next column tile while we do the epilogue
        if (ct + 1 < N_COLTILES) {
            issue_chunk(ct + 1, 0); issue_chunk(ct + 1, 1); issue_chunk(ct + 1, 2);
        }

        // dump accumulators to smem sim tile
        const int gid = lane >> 2, tig = lane & 3;
#pragma unroll
        for (int mt = 0; mt < 4; mt++) {
            const int r0 = wM * 64 + mt * 16 + gid;
#pragma unroll
            for (int nt = 0; nt < 4; nt++) {
                const int c = wN * 32 + nt * 8 + tig * 2;
                *(float2*)&Ssim[r0 * SPAD + c] = make_float2(acc[mt][nt][0], acc[mt][nt][1]);
                *(float2*)&Ssim[(r0 + 8) * SPAD + c] = make_float2(acc[mt][nt][2], acc[mt][nt][3]);
            }
        }
        __syncthreads();

        // top-10 fold: each warp owns 16 rows
        for (int r = 0; r < 16; r++) {
            const int rowL = warp * 16 + r;
            float4 v4 = *(const float4*)&Ssim[rowL * SPAD + lane * 4];
            float vv[4] = {v4.x, v4.y, v4.z, v4.w};
#pragma unroll
            for (int c = 0; c < 4; c++) {
                float v = vv[c];
                int col = ct * BN + lane * 4 + c;
                float tv = s_val[rowL * K_NB];
                int ti = s_idx[rowL * K_NB];
                unsigned m = __ballot_sync(0xffffffffu, beats(v, col, tv, ti));
                while (m) {
                    int src = __ffs(m) - 1;
                    m &= m - 1;
                    float cv = __shfl_sync(0xffffffffu, v, src);
                    int ci = __shfl_sync(0xffffffffu, col, src);
                    if (lane == 0) {
                        float* lv = s_val + rowL * K_NB;
                        int* li = s_idx + rowL * K_NB;
                        if (beats(cv, ci, lv[0], li[0])) {
                            int j = 0;
                            while (j < K_NB - 1 && beats(cv, ci, lv[j + 1], li[j + 1])) {
                                lv[j] = lv[j + 1]; li[j] = li[j + 1]; j++;
                            }
                            lv[j] = cv; li[j] = ci;
                        }
                    }
                    __syncwarp();
                }
            }
        }
        __syncthreads();
    }

    for (int i = tid; i < BM * K_NB; i += 256)
        g_topk[((size_t)b * NPTS + rowBase) * K_NB + i] = s_idx[i];
}

// ---------------------------------------------------------------------------
// K3: zero output; K4: scatter s = 1/11 (+s at diagonal)
// ---------------------------------------------------------------------------
__global__ void zero_kernel(float4* __restrict__ out, size_t n4) {
    size_t i = (size_t)blockIdx.x * blockDim.x + threadIdx.x;
    size_t stride = (size_t)gridDim.x * blockDim.x;
    float4 z = make_float4(0.f, 0.f, 0.f, 0.f);
    for (; i < n4; i += stride) out[i] = z;
}

__global__ void scatter_kernel(float* __restrict__ out) {
    int row = blockIdx.x * blockDim.x + threadIdx.x;
    if (row >= BATCH * NPTS) return;
    int i = row & (NPTS - 1);
    float* dst = out + (size_t)row * NPTS;
    const int* idx = g_topk + (size_t)row * K_NB;
    const float s = 1.0f / 11.0f;
#pragma unroll
    for (int k = 0; k < K_NB; k++) dst[idx[k]] = s;
    dst[i] += s;
}

// ---------------------------------------------------------------------------
extern "C" void kernel_launch(void* const* d_in, const int* in_sizes, int n_in,
                              void* d_out, int out_size) {
    const float* H = (const float*)d_in[0];
    float* out = (float*)d_out;

    normsplit_kernel<<<(BATCH * NPTS * 32 + 255) / 256, 256>>>(H);

    const int smem_bytes = NSTAGE * STAGE_BYTES + BM * SPAD * 4 +
                           BM * K_NB * 8 + 1024;
    cudaFuncSetAttribute(gram_topk_kernel,
                         cudaFuncAttributeMaxDynamicSharedMemorySize, smem_bytes);
    dim3 g2(NPTS / BM, BATCH);
    gram_topk_kernel<<<g2, 256, smem_bytes>>>();

    size_t n4 = (size_t)BATCH * NPTS * NPTS / 4;
    zero_kernel<<<16384, 256>>>((float4*)out, n4);

    scatter_kernel<<<(BATCH * NPTS + 255) / 256, 256>>>(out);
}